// round 15
// baseline (speedup 1.0000x reference)
#include <cuda_runtime.h>
#include <cuda_bf16.h>
#include <cstdint>

#define D_IN    3072
#define H1      32
#define OUT_N   10
#define M_TILE  128
#define KC      64              // fp32 K per chunk
#define NKB     (D_IN / KC)    // 48
#define NT      512            // 256 producers + 256 consumers
#define NC      256            // consumer thread count
#define N_ROWS  32768

// byte offsets from 1024-aligned smem base
#define SM_A      0             // 2 x 32768  (A bf16: 128 rows x [hi 16K | lo 16K])
#define SM_B      65536         // 2 x 8192   (B bf16: 32 rows x [hi 4K | lo 4K])
#define SM_SUM    81920         // 128 f
#define SM_SQ     82432         // 128 f
#define SM_W2     82944         // 32*32 f
#define SM_W3     87040         // 10*32 f
#define SM_B1     88320
#define SM_B2     88448
#define SM_B3     88576
#define SM_SC     88704
#define SM_BYTES  (88832 + 1024)

#define SWZ(o) ((o) ^ (((o) >> 3) & 0x70))

// ---------------------------------------------------------------------------
// helpers
// ---------------------------------------------------------------------------
__device__ __forceinline__ uint32_t smem_u32(const void* p) {
    uint32_t a;
    asm("{ .reg .u64 t; cvta.to.shared.u64 t, %1; cvt.u32.u64 %0, t; }"
        : "=r"(a) : "l"(p));
    return a;
}
__device__ __forceinline__ unsigned long long pk(float a, float b) {
    unsigned long long r;
    asm("mov.b64 %0, {%1, %2};" : "=l"(r) : "f"(a), "f"(b));
    return r;
}
__device__ __forceinline__ void add2(unsigned long long& d, unsigned long long a) {
    asm("add.rn.f32x2 %0, %1, %0;" : "+l"(d) : "l"(a));
}
__device__ __forceinline__ void fma2(unsigned long long& d,
                                     unsigned long long a, unsigned long long b) {
    asm("fma.rn.f32x2 %0, %1, %2, %0;" : "+l"(d) : "l"(a), "l"(b));
}
__device__ __forceinline__ float lohi(unsigned long long v) {
    union { unsigned long long u; float2 f; } t; t.u = v;
    return t.f.x + t.f.y;
}
__device__ __forceinline__ void sts128(uint32_t addr, const uint32_t* r) {
    asm volatile("st.shared.v4.b32 [%0], {%1,%2,%3,%4};"
                 :: "r"(addr), "r"(r[0]), "r"(r[1]), "r"(r[2]), "r"(r[3]) : "memory");
}
// 8 consecutive fp32 -> 4 u32 bf16-hi pairs + 4 u32 bf16-lo pairs (k order kept)
__device__ __forceinline__ void cvt8(float4 a, float4 b, uint32_t* h, uint32_t* l) {
    float v[8] = {a.x, a.y, a.z, a.w, b.x, b.y, b.z, b.w};
    #pragma unroll
    for (int k = 0; k < 4; k++) {
        float v0 = v[2 * k], v1 = v[2 * k + 1];
        uint32_t hw;
        asm("cvt.rn.bf16x2.f32 %0, %1, %2;" : "=r"(hw) : "f"(v1), "f"(v0)); // lo = v0
        float h0 = __uint_as_float(hw << 16);
        float h1 = __uint_as_float(hw & 0xffff0000u);
        float l0 = v0 - h0, l1 = v1 - h1;
        uint32_t lw;
        asm("cvt.rn.bf16x2.f32 %0, %1, %2;" : "=r"(lw) : "f"(l1), "f"(l0));
        h[k] = hw; l[k] = lw;
    }
}
__device__ __forceinline__ void ldm4(uint32_t* r, uint32_t addr) {
    asm volatile("ldmatrix.sync.aligned.m8n8.x4.shared.b16 {%0,%1,%2,%3}, [%4];"
                 : "=r"(r[0]), "=r"(r[1]), "=r"(r[2]), "=r"(r[3]) : "r"(addr));
}
__device__ __forceinline__ void mma_bf16(float* d, const uint32_t* a,
                                         const uint32_t* b) {
    asm volatile(
        "mma.sync.aligned.m16n8k16.row.col.f32.bf16.bf16.f32 "
        "{%0,%1,%2,%3}, {%4,%5,%6,%7}, {%8,%9}, {%0,%1,%2,%3};"
        : "+f"(d[0]), "+f"(d[1]), "+f"(d[2]), "+f"(d[3])
        : "r"(a[0]), "r"(a[1]), "r"(a[2]), "r"(a[3]), "r"(b[0]), "r"(b[1]));
}

// ---------------------------------------------------------------------------
// Fused: warp-specialized producers (LDG/stats/cvt/STS) + consumers (HMMA)
// ---------------------------------------------------------------------------
__global__ __launch_bounds__(NT, 2) void fused_kernel(
    const float* __restrict__ x,  const float* __restrict__ w1,
    const float* __restrict__ b1, const float* __restrict__ w2,
    const float* __restrict__ b2, const float* __restrict__ w3,
    const float* __restrict__ b3, float* __restrict__ out)
{
    extern __shared__ char smraw[];
    const uint32_t sb_u = smem_u32(smraw);
    const uint32_t sb   = (sb_u + 1023u) & ~1023u;
    char* smb = smraw + (sb - sb_u);

    float* sumS = (float*)(smb + SM_SUM);
    float* sqS  = (float*)(smb + SM_SQ);
    float* w2S  = (float*)(smb + SM_W2);
    float* w3S  = (float*)(smb + SM_W3);
    float* b1S  = (float*)(smb + SM_B1);
    float* b2S  = (float*)(smb + SM_B2);
    float* b3S  = (float*)(smb + SM_B3);
    float* ScS  = (float*)(smb + SM_SC);

    const int tid  = threadIdx.x;
    const bool is_prod = tid >= NC;
    const size_t rowbase = (size_t)blockIdx.x * M_TILE;

    // small weights to smem (all threads)
    for (int i = tid; i < H1 * H1; i += NT)    w2S[i] = w2[i];
    for (int i = tid; i < OUT_N * H1; i += NT) w3S[i] = w3[i];
    if (tid < H1) { b1S[tid] = b1[tid]; b2S[tid] = b2[tid]; }
    if (tid < OUT_N) b3S[tid] = b3[tid];

    // ===== producer state =====
    const int ptid = tid - NC;
    const int seg  = ptid & 7;          // 8-fp32 segment
    const int rgrp = ptid >> 3;         // 0..31
    unsigned long long s2[4] = {0,0,0,0}, q2[4] = {0,0,0,0};
    unsigned long long ws2 = 0;

    // ===== consumer state =====
    const int wid  = tid >> 5;          // consumer warps 0..7
    const int lane = tid & 31;
    float acc[4][4];
    #pragma unroll
    for (int n = 0; n < 4; n++)
        #pragma unroll
        for (int q = 0; q < 4; q++) acc[n][q] = 0.f;
    const uint32_t a_row = (uint32_t)(16 * wid + (lane & 15));
    const uint32_t a_kad = ((lane >> 4) & 1) * 16;
    const uint32_t b_r0  = (uint32_t)((lane & 7) + ((lane >> 4) & 1) * 8);
    const uint32_t b_kad = ((lane >> 3) & 1) * 16;

    // ---- prologue: producers fill chunk 0 into buffer 0 ----
    if (is_prod) {
        const uint32_t Ab = sb + SM_A;
        const uint32_t Bb = sb + SM_B;
        const int k0 = 0;
        const float* s0 = x + (rowbase + rgrp) * D_IN + k0 + seg * 8;
        float4 xa = *(const float4*)s0, xb = *(const float4*)(s0 + 4);
        #pragma unroll
        for (int i = 0; i < 4; i++) {
            float4 na, nb;
            if (i < 3) {
                const float* sn = x + (rowbase + rgrp + 32 * (i + 1)) * D_IN + k0 + seg * 8;
                na = *(const float4*)sn; nb = *(const float4*)(sn + 4);
            }
            unsigned long long p0 = pk(xa.x, xa.y), p1 = pk(xa.z, xa.w);
            unsigned long long p2 = pk(xb.x, xb.y), p3 = pk(xb.z, xb.w);
            add2(s2[i], p0); add2(s2[i], p1); add2(s2[i], p2); add2(s2[i], p3);
            fma2(q2[i], p0, p0); fma2(q2[i], p1, p1);
            fma2(q2[i], p2, p2); fma2(q2[i], p3, p3);
            uint32_t h[4], l[4];
            cvt8(xa, xb, h, l);
            uint32_t off = (uint32_t)(rgrp + 32 * i) * 128 + seg * 16;
            sts128(Ab + SWZ(off), h);
            sts128(Ab + 16384 + SWZ(off), l);
            xa = na; xb = nb;
        }
        const float* wsrc = w1 + (size_t)rgrp * D_IN + k0 + seg * 8;
        float4 wa = *(const float4*)wsrc, wb = *(const float4*)(wsrc + 4);
        unsigned long long p0 = pk(wa.x, wa.y), p1 = pk(wa.z, wa.w);
        unsigned long long p2 = pk(wb.x, wb.y), p3 = pk(wb.z, wb.w);
        add2(ws2, p0); add2(ws2, p1); add2(ws2, p2); add2(ws2, p3);
        uint32_t h[4], l[4];
        cvt8(wa, wb, h, l);
        uint32_t off = (uint32_t)rgrp * 128 + seg * 16;
        sts128(Bb + SWZ(off), h);
        sts128(Bb + 4096 + SWZ(off), l);
    }
    __syncthreads();

    // ---- main loop: producers chunk kb, consumers chunk kb-1 ----
    for (int kb = 1; kb < NKB; kb++) {
        if (is_prod) {
            const int p = kb & 1;
            const uint32_t Ab = sb + SM_A + p * 32768;
            const uint32_t Bb = sb + SM_B + p * 8192;
            const int k0 = kb * KC;
            const float* s0 = x + (rowbase + rgrp) * D_IN + k0 + seg * 8;
            float4 xa = *(const float4*)s0, xb = *(const float4*)(s0 + 4);
            #pragma unroll
            for (int i = 0; i < 4; i++) {
                float4 na, nb;
                if (i < 3) {
                    const float* sn = x + (rowbase + rgrp + 32 * (i + 1)) * D_IN
                                        + k0 + seg * 8;
                    na = *(const float4*)sn; nb = *(const float4*)(sn + 4);
                }
                unsigned long long p0 = pk(xa.x, xa.y), p1 = pk(xa.z, xa.w);
                unsigned long long p2 = pk(xb.x, xb.y), p3 = pk(xb.z, xb.w);
                add2(s2[i], p0); add2(s2[i], p1); add2(s2[i], p2); add2(s2[i], p3);
                fma2(q2[i], p0, p0); fma2(q2[i], p1, p1);
                fma2(q2[i], p2, p2); fma2(q2[i], p3, p3);
                uint32_t h[4], l[4];
                cvt8(xa, xb, h, l);
                uint32_t off = (uint32_t)(rgrp + 32 * i) * 128 + seg * 16;
                sts128(Ab + SWZ(off), h);
                sts128(Ab + 16384 + SWZ(off), l);
                xa = na; xb = nb;
            }
            const float* wsrc = w1 + (size_t)rgrp * D_IN + k0 + seg * 8;
            float4 wa = *(const float4*)wsrc, wb = *(const float4*)(wsrc + 4);
            unsigned long long p0 = pk(wa.x, wa.y), p1 = pk(wa.z, wa.w);
            unsigned long long p2 = pk(wb.x, wb.y), p3 = pk(wb.z, wb.w);
            add2(ws2, p0); add2(ws2, p1); add2(ws2, p2); add2(ws2, p3);
            uint32_t h[4], l[4];
            cvt8(wa, wb, h, l);
            uint32_t off = (uint32_t)rgrp * 128 + seg * 16;
            sts128(Bb + SWZ(off), h);
            sts128(Bb + 4096 + SWZ(off), l);
        } else {
            const int p = (kb - 1) & 1;
            const uint32_t Ab = sb + SM_A + p * 32768;
            const uint32_t Bb = sb + SM_B + p * 8192;
            #pragma unroll
            for (int j = 0; j < 4; j++) {
                uint32_t ah[4], al[4];
                uint32_t aoff = SWZ(a_row * 128 + (uint32_t)j * 32 + a_kad);
                ldm4(ah, Ab + aoff);
                ldm4(al, Ab + 16384 + aoff);
                uint32_t bh[2][4], bl[2][4];
                #pragma unroll
                for (int nb = 0; nb < 2; nb++) {
                    uint32_t boff = SWZ(((uint32_t)nb * 16 + b_r0) * 128
                                        + (uint32_t)j * 32 + b_kad);
                    ldm4(bh[nb], Bb + boff);
                    ldm4(bl[nb], Bb + 4096 + boff);
                }
                #pragma unroll
                for (int n = 0; n < 4; n++) {
                    const uint32_t* bhn = &bh[n >> 1][(n & 1) * 2];
                    const uint32_t* bln = &bl[n >> 1][(n & 1) * 2];
                    mma_bf16(acc[n], ah, bhn);      // hi . hi
                    mma_bf16(acc[n], al, bhn);      // lo . hi
                    mma_bf16(acc[n], ah, bln);      // hi . lo
                }
            }
        }
        __syncthreads();
    }

    // ---- tail: consumers MMA last chunk; producers store stats ----
    if (!is_prod) {
        const int p = (NKB - 1) & 1;
        const uint32_t Ab = sb + SM_A + p * 32768;
        const uint32_t Bb = sb + SM_B + p * 8192;
        #pragma unroll
        for (int j = 0; j < 4; j++) {
            uint32_t ah[4], al[4];
            uint32_t aoff = SWZ(a_row * 128 + (uint32_t)j * 32 + a_kad);
            ldm4(ah, Ab + aoff);
            ldm4(al, Ab + 16384 + aoff);
            uint32_t bh[2][4], bl[2][4];
            #pragma unroll
            for (int nb = 0; nb < 2; nb++) {
                uint32_t boff = SWZ(((uint32_t)nb * 16 + b_r0) * 128
                                    + (uint32_t)j * 32 + b_kad);
                ldm4(bh[nb], Bb + boff);
                ldm4(bl[nb], Bb + 4096 + boff);
            }
            #pragma unroll
            for (int n = 0; n < 4; n++) {
                const uint32_t* bhn = &bh[n >> 1][(n & 1) * 2];
                const uint32_t* bln = &bl[n >> 1][(n & 1) * 2];
                mma_bf16(acc[n], ah, bhn);
                mma_bf16(acc[n], al, bhn);
                mma_bf16(acc[n], ah, bln);
            }
        }
    } else {
        #pragma unroll
        for (int i = 0; i < 4; i++) {
            float s = lohi(s2[i]), q = lohi(q2[i]);
            #pragma unroll
            for (int m = 1; m < 8; m <<= 1) {
                s += __shfl_xor_sync(0xffffffffu, s, m);
                q += __shfl_xor_sync(0xffffffffu, q, m);
            }
            if (seg == 0) { sumS[rgrp + 32 * i] = s; sqS[rgrp + 32 * i] = q; }
        }
        float sw = lohi(ws2);
        #pragma unroll
        for (int m = 1; m < 8; m <<= 1)
            sw += __shfl_xor_sync(0xffffffffu, sw, m);
        if (seg == 0) ScS[rgrp] = sw;
    }
    __syncthreads();

    // ---- consumers stage accumulators to smem (reuse A buffer 0) ----
    float* dotS = (float*)(smb + SM_A);          // 128 x 33 floats
    if (!is_prod) {
        const int g = lane >> 2, t = lane & 3;
        #pragma unroll
        for (int n = 0; n < 4; n++) {
            int r0 = 16 * wid + g, c = n * 8 + t * 2;
            dotS[r0 * 33 + c]       = acc[n][0];
            dotS[r0 * 33 + c + 1]   = acc[n][1];
            dotS[(r0+8) * 33 + c]   = acc[n][2];
            dotS[(r0+8) * 33 + c+1] = acc[n][3];
        }
    }
    __syncthreads();

    // ---- epilogue: one thread per row ----
    if (tid < M_TILE) {
        const int row = tid;
        const float invD  = 1.0f / (float)D_IN;
        const float invDm = 1.0f / (float)(D_IN - 1);
        float mean = sumS[row] * invD;
        float var  = (sqS[row] - (float)D_IN * mean * mean) * invDm;
        float rstd = rsqrtf(var);

        float y[32];
        #pragma unroll
        for (int j = 0; j < 32; j++) {
            float d = dotS[row * 33 + j];
            float v = fmaf(d - mean * ScS[j], rstd, b1S[j]);
            y[j] = fmaxf(v, 0.01f * v);
        }
        float a2[32];
        #pragma unroll
        for (int j = 0; j < 32; j++) {
            float s = b2S[j];
            #pragma unroll
            for (int i = 0; i < 32; i++) s = fmaf(w2S[j * 32 + i], y[i], s);
            a2[j] = fmaxf(s, 0.01f * s);
        }
        float a3[OUT_N];
        #pragma unroll
        for (int j = 0; j < OUT_N; j++) {
            float s = b3S[j];
            #pragma unroll
            for (int i = 0; i < 32; i++) s = fmaf(w3S[j * 32 + i], a2[i], s);
            a3[j] = fmaxf(s, 0.01f * s);
        }
        float* op = out + (rowbase + row) * OUT_N;
        #pragma unroll
        for (int j = 0; j < OUT_N; j += 2)
            *(float2*)(op + j) = make_float2(a3[j], a3[j + 1]);
    }
}

// ---------------------------------------------------------------------------
extern "C" void kernel_launch(void* const* d_in, const int* in_sizes, int n_in,
                              void* d_out, int out_size) {
    const float* x  = (const float*)d_in[0];
    const float* w1 = (const float*)d_in[1];
    const float* b1 = (const float*)d_in[2];
    const float* w2 = (const float*)d_in[3];
    const float* b2 = (const float*)d_in[4];
    const float* w3 = (const float*)d_in[5];
    const float* b3 = (const float*)d_in[6];
    float* out = (float*)d_out;

    cudaFuncSetAttribute(fused_kernel,
                         cudaFuncAttributeMaxDynamicSharedMemorySize, SM_BYTES);

    fused_kernel<<<N_ROWS / M_TILE, NT, SM_BYTES>>>(x, w1, b1, w2, b2, w3, b3, out);
}

// round 16
// speedup vs baseline: 1.5735x; 1.5735x over previous
#include <cuda_runtime.h>
#include <cuda_bf16.h>
#include <cstdint>

#define D_IN    3072
#define H1      32
#define OUT_N   10
#define M_TILE  128
#define KC      64              // fp32 K per chunk
#define NKB     (D_IN / KC)    // 48
#define NT      384            // warps 0-7: cvt+MMA ; warps 8-11: cvt only
#define N_ROWS  32768

// byte offsets from 1024-aligned smem base
#define SM_A      0             // 2 x 32768  (A bf16: 128 rows x [hi 16K | lo 16K])
#define SM_B      65536         // 2 x 8192   (B bf16: 32 rows x [hi 4K | lo 4K])
#define SM_SUM    81920         // 128 f
#define SM_SQ     82432         // 128 f
#define SM_W2     82944         // 32*32 f
#define SM_W3     87040         // 10*32 f
#define SM_B1     88320
#define SM_B2     88448
#define SM_B3     88576
#define SM_SC     88704
#define SM_BYTES  (88832 + 1024)

#define SWZ(o) ((o) ^ (((o) >> 3) & 0x70))

// ---------------------------------------------------------------------------
// helpers
// ---------------------------------------------------------------------------
__device__ __forceinline__ uint32_t smem_u32(const void* p) {
    uint32_t a;
    asm("{ .reg .u64 t; cvta.to.shared.u64 t, %1; cvt.u32.u64 %0, t; }"
        : "=r"(a) : "l"(p));
    return a;
}
__device__ __forceinline__ unsigned long long pk(float a, float b) {
    unsigned long long r;
    asm("mov.b64 %0, {%1, %2};" : "=l"(r) : "f"(a), "f"(b));
    return r;
}
__device__ __forceinline__ void add2(unsigned long long& d, unsigned long long a) {
    asm("add.rn.f32x2 %0, %1, %0;" : "+l"(d) : "l"(a));
}
__device__ __forceinline__ void fma2(unsigned long long& d,
                                     unsigned long long a, unsigned long long b) {
    asm("fma.rn.f32x2 %0, %1, %2, %0;" : "+l"(d) : "l"(a), "l"(b));
}
__device__ __forceinline__ float lohi(unsigned long long v) {
    union { unsigned long long u; float2 f; } t; t.u = v;
    return t.f.x + t.f.y;
}
__device__ __forceinline__ void sts128(uint32_t addr, const uint32_t* r) {
    asm volatile("st.shared.v4.b32 [%0], {%1,%2,%3,%4};"
                 :: "r"(addr), "r"(r[0]), "r"(r[1]), "r"(r[2]), "r"(r[3]) : "memory");
}
// 8 consecutive fp32 -> 4 u32 bf16-hi pairs + 4 u32 bf16-lo pairs (k order kept)
__device__ __forceinline__ void cvt8(float4 a, float4 b, uint32_t* h, uint32_t* l) {
    float v[8] = {a.x, a.y, a.z, a.w, b.x, b.y, b.z, b.w};
    #pragma unroll
    for (int k = 0; k < 4; k++) {
        float v0 = v[2 * k], v1 = v[2 * k + 1];
        uint32_t hw;
        asm("cvt.rn.bf16x2.f32 %0, %1, %2;" : "=r"(hw) : "f"(v1), "f"(v0)); // lo = v0
        float h0 = __uint_as_float(hw << 16);
        float h1 = __uint_as_float(hw & 0xffff0000u);
        float l0 = v0 - h0, l1 = v1 - h1;
        uint32_t lw;
        asm("cvt.rn.bf16x2.f32 %0, %1, %2;" : "=r"(lw) : "f"(l1), "f"(l0));
        h[k] = hw; l[k] = lw;
    }
}
__device__ __forceinline__ void ldm4(uint32_t* r, uint32_t addr) {
    asm volatile("ldmatrix.sync.aligned.m8n8.x4.shared.b16 {%0,%1,%2,%3}, [%4];"
                 : "=r"(r[0]), "=r"(r[1]), "=r"(r[2]), "=r"(r[3]) : "r"(addr));
}
__device__ __forceinline__ void mma_bf16(float* d, const uint32_t* a,
                                         const uint32_t* b) {
    asm volatile(
        "mma.sync.aligned.m16n8k16.row.col.f32.bf16.bf16.f32 "
        "{%0,%1,%2,%3}, {%4,%5,%6,%7}, {%8,%9}, {%0,%1,%2,%3};"
        : "+f"(d[0]), "+f"(d[1]), "+f"(d[2]), "+f"(d[3])
        : "r"(a[0]), "r"(a[1]), "r"(a[2]), "r"(a[3]), "r"(b[0]), "r"(b[1]));
}

// ---------------------------------------------------------------------------
// Fused: hybrid-split HMMA GEMM (all warps load) + stats + norm + L1/L2/L3
// ---------------------------------------------------------------------------
__global__ __launch_bounds__(NT, 2) void fused_kernel(
    const float* __restrict__ x,  const float* __restrict__ w1,
    const float* __restrict__ b1, const float* __restrict__ w2,
    const float* __restrict__ b2, const float* __restrict__ w3,
    const float* __restrict__ b3, float* __restrict__ out)
{
    extern __shared__ char smraw[];
    const uint32_t sb_u = smem_u32(smraw);
    const uint32_t sb   = (sb_u + 1023u) & ~1023u;
    char* smb = smraw + (sb - sb_u);

    float* sumS = (float*)(smb + SM_SUM);
    float* sqS  = (float*)(smb + SM_SQ);
    float* w2S  = (float*)(smb + SM_W2);
    float* w3S  = (float*)(smb + SM_W3);
    float* b1S  = (float*)(smb + SM_B1);
    float* b2S  = (float*)(smb + SM_B2);
    float* b3S  = (float*)(smb + SM_B3);
    float* ScS  = (float*)(smb + SM_SC);

    const int tid  = threadIdx.x;
    const bool is_mma = tid < 256;
    const size_t rowbase = (size_t)blockIdx.x * M_TILE;

    // small weights to smem (all threads)
    for (int i = tid; i < H1 * H1; i += NT)    w2S[i] = w2[i];
    for (int i = tid; i < OUT_N * H1; i += NT) w3S[i] = w3[i];
    if (tid < H1) { b1S[tid] = b1[tid]; b2S[tid] = b2[tid]; }
    if (tid < OUT_N) b3S[tid] = b3[tid];

    // ===== mma-group state (tid < 256) =====
    const int wid  = tid >> 5;          // 0..7 (mma warps)
    const int lane = tid & 31;
    const int r0   = tid >> 3;          // A rows r0, r0+32   (rows 0..63)
    const int seg  = tid & 7;           // shared by both groups (tid&7)
    float acc[4][4];
    #pragma unroll
    for (int n = 0; n < 4; n++)
        #pragma unroll
        for (int q = 0; q < 4; q++) acc[n][q] = 0.f;
    const uint32_t a_row = (uint32_t)(16 * wid + (lane & 15));
    const uint32_t a_kad = ((lane >> 4) & 1) * 16;
    const uint32_t b_r0  = (uint32_t)((lane & 7) + ((lane >> 4) & 1) * 8);
    const uint32_t b_kad = ((lane >> 3) & 1) * 16;

    // ===== prod-group state (tid >= 256) =====
    const int j  = tid - 256;           // 0..127
    const int jr = j >> 3;              // 0..15 : A rows 64+jr+16t, w rows jr, jr+16

    // stats accumulators (f32x2)
    unsigned long long s2[4] = {0,0,0,0}, q2[4] = {0,0,0,0};
    unsigned long long ws2[2] = {0,0};

    for (int kb = 0; kb < NKB; kb++) {
        const int p  = kb & 1;
        const int k0 = kb * KC;
        const uint32_t Ab = sb + SM_A + p * 32768;
        const uint32_t Bb = sb + SM_B + p * 8192;

        if (is_mma) {
            // ---- 2 A slots: rows r0, r0+32 ----
            const float* s0 = x + (rowbase + r0) * D_IN + k0 + seg * 8;
            const float* s1 = x + (rowbase + r0 + 32) * D_IN + k0 + seg * 8;
            float4 a0 = *(const float4*)s0, b0 = *(const float4*)(s0 + 4);
            float4 a1 = *(const float4*)s1, b1v = *(const float4*)(s1 + 4);
            {
                unsigned long long p0 = pk(a0.x, a0.y), p1 = pk(a0.z, a0.w);
                unsigned long long p2 = pk(b0.x, b0.y), p3 = pk(b0.z, b0.w);
                add2(s2[0], p0); add2(s2[0], p1); add2(s2[0], p2); add2(s2[0], p3);
                fma2(q2[0], p0, p0); fma2(q2[0], p1, p1);
                fma2(q2[0], p2, p2); fma2(q2[0], p3, p3);
                uint32_t h[4], l[4];
                cvt8(a0, b0, h, l);
                uint32_t off = (uint32_t)r0 * 128 + seg * 16;
                sts128(Ab + SWZ(off), h);
                sts128(Ab + 16384 + SWZ(off), l);
            }
            {
                unsigned long long p0 = pk(a1.x, a1.y), p1 = pk(a1.z, a1.w);
                unsigned long long p2 = pk(b1v.x, b1v.y), p3 = pk(b1v.z, b1v.w);
                add2(s2[1], p0); add2(s2[1], p1); add2(s2[1], p2); add2(s2[1], p3);
                fma2(q2[1], p0, p0); fma2(q2[1], p1, p1);
                fma2(q2[1], p2, p2); fma2(q2[1], p3, p3);
                uint32_t h[4], l[4];
                cvt8(a1, b1v, h, l);
                uint32_t off = (uint32_t)(r0 + 32) * 128 + seg * 16;
                sts128(Ab + SWZ(off), h);
                sts128(Ab + 16384 + SWZ(off), l);
            }
        } else {
            // ---- 4 A slots: rows 64+jr+16t ----
            float4 xa[4], xb[4];
            #pragma unroll
            for (int t = 0; t < 4; t++) {
                const float* s = x + (rowbase + 64 + jr + 16 * t) * D_IN + k0 + seg * 8;
                xa[t] = *(const float4*)s;
                xb[t] = *(const float4*)(s + 4);
            }
            #pragma unroll
            for (int t = 0; t < 4; t++) {
                unsigned long long p0 = pk(xa[t].x, xa[t].y), p1 = pk(xa[t].z, xa[t].w);
                unsigned long long p2 = pk(xb[t].x, xb[t].y), p3 = pk(xb[t].z, xb[t].w);
                add2(s2[t], p0); add2(s2[t], p1); add2(s2[t], p2); add2(s2[t], p3);
                fma2(q2[t], p0, p0); fma2(q2[t], p1, p1);
                fma2(q2[t], p2, p2); fma2(q2[t], p3, p3);
                uint32_t h[4], l[4];
                cvt8(xa[t], xb[t], h, l);
                uint32_t off = (uint32_t)(64 + jr + 16 * t) * 128 + seg * 16;
                sts128(Ab + SWZ(off), h);
                sts128(Ab + 16384 + SWZ(off), l);
            }
            // ---- 2 w slots: rows jr, jr+16 ----
            #pragma unroll
            for (int t = 0; t < 2; t++) {
                const float* s = w1 + (size_t)(jr + 16 * t) * D_IN + k0 + seg * 8;
                float4 wa = *(const float4*)s, wb = *(const float4*)(s + 4);
                unsigned long long p0 = pk(wa.x, wa.y), p1 = pk(wa.z, wa.w);
                unsigned long long p2 = pk(wb.x, wb.y), p3 = pk(wb.z, wb.w);
                add2(ws2[t], p0); add2(ws2[t], p1); add2(ws2[t], p2); add2(ws2[t], p3);
                uint32_t h[4], l[4];
                cvt8(wa, wb, h, l);
                uint32_t off = (uint32_t)(jr + 16 * t) * 128 + seg * 16;
                sts128(Bb + SWZ(off), h);
                sts128(Bb + 4096 + SWZ(off), l);
            }
        }
        __syncthreads();

        // ---- MMA on buffer p (mma group only; prod warps run ahead to LDG) ----
        if (is_mma) {
            #pragma unroll
            for (int jj = 0; jj < 4; jj++) {
                uint32_t ah[4], al[4];
                uint32_t aoff = SWZ(a_row * 128 + (uint32_t)jj * 32 + a_kad);
                ldm4(ah, Ab + aoff);
                ldm4(al, Ab + 16384 + aoff);
                uint32_t bh[2][4], bl[2][4];
                #pragma unroll
                for (int nb = 0; nb < 2; nb++) {
                    uint32_t boff = SWZ(((uint32_t)nb * 16 + b_r0) * 128
                                        + (uint32_t)jj * 32 + b_kad);
                    ldm4(bh[nb], Bb + boff);
                    ldm4(bl[nb], Bb + 4096 + boff);
                }
                #pragma unroll
                for (int n = 0; n < 4; n++) {
                    const uint32_t* bhn = &bh[n >> 1][(n & 1) * 2];
                    const uint32_t* bln = &bl[n >> 1][(n & 1) * 2];
                    mma_bf16(acc[n], ah, bhn);      // hi . hi
                    mma_bf16(acc[n], al, bhn);      // lo . hi
                    mma_bf16(acc[n], ah, bln);      // hi . lo
                }
            }
        }
    }

    // ---- stats reductions over the 8 seg lanes ----
    if (is_mma) {
        #pragma unroll
        for (int i = 0; i < 2; i++) {
            float s = lohi(s2[i]), q = lohi(q2[i]);
            #pragma unroll
            for (int m = 1; m < 8; m <<= 1) {
                s += __shfl_xor_sync(0xffffffffu, s, m);
                q += __shfl_xor_sync(0xffffffffu, q, m);
            }
            if (seg == 0) { sumS[r0 + 32 * i] = s; sqS[r0 + 32 * i] = q; }
        }
    } else {
        #pragma unroll
        for (int t = 0; t < 4; t++) {
            float s = lohi(s2[t]), q = lohi(q2[t]);
            #pragma unroll
            for (int m = 1; m < 8; m <<= 1) {
                s += __shfl_xor_sync(0xffffffffu, s, m);
                q += __shfl_xor_sync(0xffffffffu, q, m);
            }
            if (seg == 0) { sumS[64 + jr + 16 * t] = s; sqS[64 + jr + 16 * t] = q; }
        }
        #pragma unroll
        for (int t = 0; t < 2; t++) {
            float s = lohi(ws2[t]);
            #pragma unroll
            for (int m = 1; m < 8; m <<= 1)
                s += __shfl_xor_sync(0xffffffffu, s, m);
            if (seg == 0) ScS[jr + 16 * t] = s;
        }
    }

    // ---- mma group stages accumulators to smem (buffer 0: last MMA read of
    //      buffer 0 was chunk 46, complete before sync(47) for all warps) ----
    float* dotS = (float*)(smb + SM_A);          // 128 x 33 floats
    if (is_mma) {
        const int g = lane >> 2, t = lane & 3;
        #pragma unroll
        for (int n = 0; n < 4; n++) {
            int rr = 16 * wid + g, c = n * 8 + t * 2;
            dotS[rr * 33 + c]       = acc[n][0];
            dotS[rr * 33 + c + 1]   = acc[n][1];
            dotS[(rr+8) * 33 + c]   = acc[n][2];
            dotS[(rr+8) * 33 + c+1] = acc[n][3];
        }
    }
    __syncthreads();

    // ---- epilogue: one thread per row ----
    if (tid < M_TILE) {
        const int row = tid;
        const float invD  = 1.0f / (float)D_IN;
        const float invDm = 1.0f / (float)(D_IN - 1);
        float mean = sumS[row] * invD;
        float var  = (sqS[row] - (float)D_IN * mean * mean) * invDm;
        float rstd = rsqrtf(var);

        float y[32];
        #pragma unroll
        for (int jj = 0; jj < 32; jj++) {
            float d = dotS[row * 33 + jj];
            float v = fmaf(d - mean * ScS[jj], rstd, b1S[jj]);
            y[jj] = fmaxf(v, 0.01f * v);
        }
        float a2[32];
        #pragma unroll
        for (int jj = 0; jj < 32; jj++) {
            float s = b2S[jj];
            #pragma unroll
            for (int i = 0; i < 32; i++) s = fmaf(w2S[jj * 32 + i], y[i], s);
            a2[jj] = fmaxf(s, 0.01f * s);
        }
        float a3[OUT_N];
        #pragma unroll
        for (int jj = 0; jj < OUT_N; jj++) {
            float s = b3S[jj];
            #pragma unroll
            for (int i = 0; i < 32; i++) s = fmaf(w3S[jj * 32 + i], a2[i], s);
            a3[jj] = fmaxf(s, 0.01f * s);
        }
        float* op = out + (rowbase + row) * OUT_N;
        #pragma unroll
        for (int jj = 0; jj < OUT_N; jj += 2)
            *(float2*)(op + jj) = make_float2(a3[jj], a3[jj + 1]);
    }
}

// ---------------------------------------------------------------------------
extern "C" void kernel_launch(void* const* d_in, const int* in_sizes, int n_in,
                              void* d_out, int out_size) {
    const float* x  = (const float*)d_in[0];
    const float* w1 = (const float*)d_in[1];
    const float* b1 = (const float*)d_in[2];
    const float* w2 = (const float*)d_in[3];
    const float* b2 = (const float*)d_in[4];
    const float* w3 = (const float*)d_in[5];
    const float* b3 = (const float*)d_in[6];
    float* out = (float*)d_out;

    cudaFuncSetAttribute(fused_kernel,
                         cudaFuncAttributeMaxDynamicSharedMemorySize, SM_BYTES);

    fused_kernel<<<N_ROWS / M_TILE, NT, SM_BYTES>>>(x, w1, b1, w2, b2, w3, b3, out);
}